// round 13
// baseline (speedup 1.0000x reference)
#include <cuda_runtime.h>
#include <cuda_fp16.h>
#include <cuda_bf16.h>

#define Bz 256
#define Sz 512
#define Ez 100
#define Hz 64
#define Gz 256      // 4*H
#define Vz 50000
#define VP 50048    // padded vocab rows (391*128)
#define NC 512      // 2 dirs * 256 entries
#define KPH 112     // padded K in halfs

// Table layout: [v][dir][cell e][gate i,f,g,o]  (gate-interleaved), fp16
__device__ __half g_tableh[(size_t)VP * NC];      // 51.2 MB (L2-resident)
__device__ __half g_embh[(size_t)VP * KPH];       // padded fp16 embeddings
__device__ __half g_wihh[2 * 256 * KPH];          // permuted fp16 W_ih
__device__ float  g_hfin[2 * Bz * Hz];

// f32-accumulator MMA
#define MMA16816(c0,c1,c2,c3, a0,a1,a2,a3, b0,b1) \
    asm("mma.sync.aligned.m16n8k16.row.col.f32.f16.f16.f32 " \
        "{%0,%1,%2,%3}, {%4,%5,%6,%7}, {%8,%9}, {%0,%1,%2,%3};" \
        : "+f"(c0), "+f"(c1), "+f"(c2), "+f"(c3) \
        : "r"(a0), "r"(a1), "r"(a2), "r"(a3), "r"(b0), "r"(b1))

// packed sigmoid: sigm(x) = 0.5*tanh(0.5x) + 0.5  (f16x2)
#define SIGM2(dst, src, h05) \
    asm("{ .reg .b32 tmp;\n\t" \
        "mul.f16x2 tmp, %1, %2;\n\t" \
        "tanh.approx.f16x2 tmp, tmp;\n\t" \
        "fma.rn.f16x2 %0, tmp, %2, %2; }" \
        : "=r"(dst) : "r"(src), "r"(h05))

#define PRMT(d, a, b, sel) \
    asm("prmt.b32 %0, %1, %2, %3;" : "=r"(d) : "r"(a), "r"(b), "n"(sel))

__device__ __forceinline__ unsigned int tanh2_ap(unsigned int x) {
    unsigned int y;
    asm("tanh.approx.f16x2 %0, %1;" : "=r"(y) : "r"(x));
    return y;
}
__device__ __forceinline__ unsigned int hadd2u(unsigned int a, unsigned int b) {
    unsigned int d;
    asm("add.rn.f16x2 %0, %1, %2;" : "=r"(d) : "r"(a), "r"(b));
    return d;
}
__device__ __forceinline__ unsigned int hmul2u(unsigned int a, unsigned int b) {
    unsigned int d;
    asm("mul.f16x2 %0, %1, %2;" : "=r"(d) : "r"(a), "r"(b));
    return d;
}
__device__ __forceinline__ unsigned int hfma2u(unsigned int a, unsigned int b,
                                               unsigned int c) {
    unsigned int d;
    asm("fma.rn.f16x2 %0, %1, %2, %3;" : "=r"(d) : "r"(a), "r"(b), "r"(c));
    return d;
}
__device__ __forceinline__ unsigned int pkf(float a, float b) {
    __half2 h = __floats2half2_rn(a, b);
    return *(unsigned int*)&h;
}

#define H05C 0x38003800u   // half2(0.5, 0.5)

// packed LSTM cell update: returns h (f16x2), updates cst (f16x2)
__device__ __forceinline__ unsigned int lstm_update(unsigned int ui, unsigned int uf,
                                                    unsigned int ug, unsigned int uo,
                                                    unsigned int& cst) {
    unsigned int si, sf, so;
    SIGM2(si, ui, H05C);
    SIGM2(sf, uf, H05C);
    SIGM2(so, uo, H05C);
    unsigned int tgg = tanh2_ap(ug);
    cst = hfma2u(sf, cst, hmul2u(si, tgg));
    return hmul2u(so, tanh2_ap(cst));
}

// ---------------------------------------------------------------------------
// Kernel 0a: convert embeddings -> fp16 padded [VP][112]
// ---------------------------------------------------------------------------
__global__ __launch_bounds__(256)
void cvt_emb(const float* __restrict__ emb)
{
    int row = blockIdx.x * 4 + (threadIdx.x >> 6);
    int q   = threadIdx.x & 63;            // half2 index within row
    if (q >= KPH / 2) return;
    __half2 v = __half2half2(__float2half(0.0f));
    if (row < Vz && q < 50) {
        float2 f = ((const float2*)emb)[(size_t)row * 50 + q];
        v = __floats2half2_rn(f.x, f.y);
    }
    ((__half2*)g_embh)[(size_t)row * (KPH / 2) + q] = v;
}

// ---------------------------------------------------------------------------
// Kernel 0b: convert W_ih -> fp16, gate-permuted rows: g_wihh[dir][cnew][112]
//            where cnew = 4*e + gate holds W_ih row gate*64 + e.
// ---------------------------------------------------------------------------
__global__ __launch_bounds__(64)
void cvt_wih(const float* __restrict__ Wf, const float* __restrict__ Wb)
{
    int dir  = blockIdx.x >> 8;
    int cnew = blockIdx.x & 255;
    int wrow = (cnew & 3) * 64 + (cnew >> 2);
    const float2* W2 = (const float2*)(dir ? Wb : Wf) + (size_t)wrow * 50;
    int q = threadIdx.x;
    if (q >= KPH / 2) return;
    __half2 v = (q < 50) ? __floats2half2_rn(W2[q].x, W2[q].y)
                         : __half2half2(__float2half(0.0f));
    ((__half2*)g_wihh)[((size_t)dir * 256 + cnew) * (KPH / 2) + q] = v;
}

// ---------------------------------------------------------------------------
// Kernel 1: vocab-table GEMM via HMMA (fp16 operands pre-converted).
// Staging = pure uint4 copies with shift-only indexing. Epilogue unchanged.
// ---------------------------------------------------------------------------
#define LDH 120    // smem row stride in halfs

__global__ __launch_bounds__(256)
void vocab_gemm(const float* __restrict__ bih_f,
                const float* __restrict__ bhh_f,
                const float* __restrict__ bih_b,
                const float* __restrict__ bhh_b)
{
    const int tid  = threadIdx.x;
    const int lane = tid & 31;
    const int w    = tid >> 5;
    const int gid  = lane >> 2;
    const int tg   = lane & 3;
    const int wm   = w & 3;
    const int wn   = w >> 2;

    const int rb = blockIdx.x * 128;
    const int cb = blockIdx.y * 64;
    const int dir = cb >> 8;
    const int gb  = cb & 255;          // column base within dir

    const float* __restrict__ bi = dir ? bih_b : bih_f;
    const float* __restrict__ bh = dir ? bhh_b : bhh_f;

    __shared__ __align__(16) __half As[128 * LDH];
    __shared__ __align__(16) __half Bs[64 * LDH];
    __shared__ float bias_s[64];

    if (tid < 64) {
        int cloc = gb + tid;
        int wrow = (cloc & 3) * 64 + (cloc >> 2);   // gate*64 + e
        bias_s[tid] = bi[wrow] + bh[wrow];
    }

    // Stage A: 128 rows x 14 uint4; 2 threads per row, 7 uint4 each
    {
        int m = tid >> 1, h = tid & 1;
        const uint4* src = (const uint4*)(g_embh + (size_t)(rb + m) * KPH) + h * 7;
        uint4* dst = (uint4*)(As + m * LDH) + h * 7;
#pragma unroll
        for (int i = 0; i < 7; i++) dst[i] = src[i];
    }
    // Stage B: 64 rows x 14 uint4; 4 threads per row
    {
        int m = tid >> 2, q0 = tid & 3;
        const uint4* src = (const uint4*)(g_wihh + ((size_t)dir * 256 + gb + m) * KPH);
        uint4* dst = (uint4*)(Bs + m * LDH);
#pragma unroll
        for (int i = 0; i < 4; i++) {
            int q = q0 + 4 * i;
            if (q < 14) dst[q] = src[q];
        }
    }
    __syncthreads();

    float acc[2][4][4];
#pragma unroll
    for (int mt = 0; mt < 2; mt++)
#pragma unroll
        for (int nt = 0; nt < 4; nt++)
#pragma unroll
            for (int i = 0; i < 4; i++) acc[mt][nt][i] = 0.0f;

#pragma unroll
    for (int kt = 0; kt < 7; kt++) {
        unsigned int a[2][4], b[4][2];
#pragma unroll
        for (int mt = 0; mt < 2; mt++) {
            int r = wm * 32 + mt * 16 + gid;
            const unsigned int* p0 = (const unsigned int*)(As + r * LDH + kt * 16 + 2 * tg);
            const unsigned int* p1 = (const unsigned int*)(As + (r + 8) * LDH + kt * 16 + 2 * tg);
            a[mt][0] = p0[0];
            a[mt][1] = p1[0];
            a[mt][2] = p0[4];
            a[mt][3] = p1[4];
        }
#pragma unroll
        for (int nt = 0; nt < 4; nt++) {
            int n = wn * 32 + nt * 8 + gid;
            const unsigned int* p = (const unsigned int*)(Bs + n * LDH + kt * 16 + 2 * tg);
            b[nt][0] = p[0];
            b[nt][1] = p[4];
        }
#pragma unroll
        for (int mt = 0; mt < 2; mt++)
#pragma unroll
            for (int nt = 0; nt < 4; nt++)
                MMA16816(acc[mt][nt][0], acc[mt][nt][1], acc[mt][nt][2], acc[mt][nt][3],
                         a[mt][0], a[mt][1], a[mt][2], a[mt][3],
                         b[nt][0], b[nt][1]);
    }

#pragma unroll
    for (int mt = 0; mt < 2; mt++) {
#pragma unroll
        for (int nt = 0; nt < 4; nt++) {
            int n = wn * 32 + nt * 8 + 2 * tg;
            float b0 = bias_s[n], b1 = bias_s[n + 1];
            int r0 = rb + wm * 32 + mt * 16 + gid;
            int r1 = r0 + 8;
            *(__half2*)&g_tableh[(size_t)r0 * NC + cb + n] =
                __floats2half2_rn(acc[mt][nt][0] + b0, acc[mt][nt][1] + b1);
            *(__half2*)&g_tableh[(size_t)r1 * NC + cb + n] =
                __floats2half2_rn(acc[mt][nt][2] + b0, acc[mt][nt][3] + b1);
        }
    }
}

// ---------------------------------------------------------------------------
// Kernel 2: LSTM recurrence (R11 base; CH=4, 128 blocks = 1 wave).
// NEW: 8 fully independent MMA accumulators (chain depth 1) + FADD merge
// tree; unconditional clamped distance-2 prefetch (no zeroing MOVs).
// ---------------------------------------------------------------------------
#define HP 72    // h smem row stride (halfs)

__global__ __launch_bounds__(256)
void lstm_rec(const int* __restrict__ x,
              const float* __restrict__ Whh_f,
              const float* __restrict__ Whh_b)
{
    const int tid  = threadIdx.x;
    const int lane = tid & 31;
    const int w    = tid >> 5;
    const int gid  = lane >> 2;
    const int tg   = lane & 3;
    const int e    = w * 8 + gid;       // owned cell
    const int n0   = 2 * tg;            // chains n0, n0+1 (real if tg<2)
    const bool real = (tg < 2);

    const int bg  = blockIdx.x;
    const int dir = blockIdx.y;
    const float* __restrict__ W = dir ? Whh_b : Whh_f;
    const __half* __restrict__ tb = g_tableh + dir * Gz;   // + v*NC + 4e

    __shared__ int toks[4][Sz];
    __shared__ __align__(16) __half h_sh[2][8 * HP];

    for (int p = tid; p < 4 * Sz; p += 256) {
        int r = p >> 9, t_ = p & 511;
        toks[r][t_] = x[(bg * 4 + r) * Sz + t_];
    }
    for (int p = tid; p < 2 * 8 * HP; p += 256)
        ((__half*)h_sh)[p] = __float2half(0.0f);

    // A fragments, permuted-gate packing, fp16:
    //   mt0 rows: gid -> i(e), gid+8 -> f(e);  mt1: g(e), o(e)
    unsigned int afr[2][4][4];
#pragma unroll
    for (int mt = 0; mt < 2; mt++) {
        const float* r0 = W + (size_t)((2 * mt)     * 64 + e) * Hz;
        const float* r1 = W + (size_t)((2 * mt + 1) * 64 + e) * Hz;
#pragma unroll
        for (int kt = 0; kt < 4; kt++) {
            int cb_ = kt * 16 + tg * 2;
            __half2 a0 = __floats2half2_rn(r0[cb_],     r0[cb_ + 1]);
            __half2 a1 = __floats2half2_rn(r1[cb_],     r1[cb_ + 1]);
            __half2 a2 = __floats2half2_rn(r0[cb_ + 8], r0[cb_ + 9]);
            __half2 a3 = __floats2half2_rn(r1[cb_ + 8], r1[cb_ + 9]);
            afr[mt][kt][0] = *(unsigned int*)&a0;
            afr[mt][kt][1] = *(unsigned int*)&a1;
            afr[mt][kt][2] = *(unsigned int*)&a2;
            afr[mt][kt][3] = *(unsigned int*)&a3;
        }
    }

    unsigned int cst = 0u;   // packed f16x2 cell state
    unsigned int hn  = 0u;

    __syncthreads();

    int t = dir ? (Sz - 1) : 0;
    const int dt = dir ? -1 : 1;
    int pb = 0;

    // 3-phase xp ring: xr[ph][chain] = uint2 {(i,f),(g,o)} fp16
    uint2 xr[3][2];
#pragma unroll
    for (int p = 0; p < 3; p++) { xr[p][0] = make_uint2(0u, 0u); xr[p][1] = make_uint2(0u, 0u); }
    if (real) {
        xr[0][0] = *(const uint2*)(tb + (size_t)toks[n0][t] * NC + 4 * e);
        xr[0][1] = *(const uint2*)(tb + (size_t)toks[n0 + 1][t] * NC + 4 * e);
        int t1 = t + dt;
        xr[1][0] = *(const uint2*)(tb + (size_t)toks[n0][t1] * NC + 4 * e);
        xr[1][1] = *(const uint2*)(tb + (size_t)toks[n0 + 1][t1] * NC + 4 * e);
    }

#define LSTM_STEP(PH) do {                                                     \
    unsigned int b0[4], b1[4];                                                 \
    _Pragma("unroll")                                                          \
    for (int kt = 0; kt < 4; kt++) {                                           \
        const unsigned int* hw =                                               \
            (const unsigned int*)(h_sh[pb] + gid * HP + kt * 16 + tg * 2);     \
        b0[kt] = hw[0];                                                        \
        b1[kt] = hw[4];                                                        \
    }                                                                          \
    float cA[4][4], cB[4][4];   /* [kt][elem], all independent */              \
    _Pragma("unroll")                                                          \
    for (int kt = 0; kt < 4; kt++)                                             \
        _Pragma("unroll")                                                      \
        for (int i = 0; i < 4; i++) { cA[kt][i] = 0.0f; cB[kt][i] = 0.0f; }    \
    MMA16816(cA[0][0], cA[0][1], cA[0][2], cA[0][3],                           \
             afr[0][0][0], afr[0][0][1], afr[0][0][2], afr[0][0][3], b0[0], b1[0]); \
    MMA16816(cA[1][0], cA[1][1], cA[1][2], cA[1][3],                           \
             afr[0][1][0], afr[0][1][1], afr[0][1][2], afr[0][1][3], b0[1], b1[1]); \
    MMA16816(cA[2][0], cA[2][1], cA[2][2], cA[2][3],                           \
             afr[0][2][0], afr[0][2][1], afr[0][2][2], afr[0][2][3], b0[2], b1[2]); \
    MMA16816(cA[3][0], cA[3][1], cA[3][2], cA[3][3],                           \
             afr[0][3][0], afr[0][3][1], afr[0][3][2], afr[0][3][3], b0[3], b1[3]); \
    {   /* prefetch for step s+2 into ring slot (PH+2)%3, clamped t */         \
        const int PH2 = (PH + 2) % 3;                                          \
        if (real) {                                                            \
            int t2 = t + 2 * dt;                                               \
            t2 = t2 < 0 ? 0 : (t2 > Sz - 1 ? Sz - 1 : t2);                     \
            xr[PH2][0] = *(const uint2*)(tb + (size_t)toks[n0][t2] * NC + 4 * e);     \
            xr[PH2][1] = *(const uint2*)(tb + (size_t)toks[n0 + 1][t2] * NC + 4 * e); \
        }                                                                      \
    }                                                                          \
    MMA16816(cB[0][0], cB[0][1], cB[0][2], cB[0][3],                           \
             afr[1][0][0], afr[1][0][1], afr[1][0][2], afr[1][0][3], b0[0], b1[0]); \
    MMA16816(cB[1][0], cB[1][1], cB[1][2], cB[1][3],                           \
             afr[1][1][0], afr[1][1][1], afr[1][1][2], afr[1][1][3], b0[1], b1[1]); \
    MMA16816(cB[2][0], cB[2][1], cB[2][2], cB[2][3],                           \
             afr[1][2][0], afr[1][2][1], afr[1][2][2], afr[1][2][3], b0[2], b1[2]); \
    MMA16816(cB[3][0], cB[3][1], cB[3][2], cB[3][3],                           \
             afr[1][3][0], afr[1][3][1], afr[1][3][2], afr[1][3][3], b0[3], b1[3]); \
    /* 3-level merge tree, then pack */                                        \
    float mA[4], mB[4];                                                        \
    _Pragma("unroll")                                                          \
    for (int i = 0; i < 4; i++) {                                              \
        mA[i] = (cA[0][i] + cA[1][i]) + (cA[2][i] + cA[3][i]);                 \
        mB[i] = (cB[0][i] + cB[1][i]) + (cB[2][i] + cB[3][i]);                 \
    }                                                                          \
    unsigned int ui = pkf(mA[0], mA[1]);                                       \
    unsigned int uf = pkf(mA[2], mA[3]);                                       \
    unsigned int ug = pkf(mB[0], mB[1]);                                       \
    unsigned int uo = pkf(mB[2], mB[3]);                                       \
    {   /* unpack xp (loaded 2 steps ago) and merge in f16 */                  \
        uint2 c0 = xr[PH][0], c1 = xr[PH][1];                                  \
        unsigned int xi, xf, xg, xo;                                           \
        PRMT(xi, c0.x, c1.x, 0x5410);                                          \
        PRMT(xf, c0.x, c1.x, 0x7632);                                          \
        PRMT(xg, c0.y, c1.y, 0x5410);                                          \
        PRMT(xo, c0.y, c1.y, 0x7632);                                          \
        ui = hadd2u(ui, xi);                                                   \
        uf = hadd2u(uf, xf);                                                   \
        ug = hadd2u(ug, xg);                                                   \
        uo = hadd2u(uo, xo);                                                   \
    }                                                                          \
    hn = lstm_update(ui, uf, ug, uo, cst);                                     \
    if (real) {                                                                \
        __half2 hh = *(__half2*)&hn;                                           \
        h_sh[pb ^ 1][n0 * HP + e]       = __low2half(hh);                      \
        h_sh[pb ^ 1][(n0 + 1) * HP + e] = __high2half(hh);                     \
    }                                                                          \
    __syncthreads();                                                           \
    pb ^= 1;                                                                   \
    t += dt;                                                                   \
} while (0)

    for (int it = 0; it < 170; it++) {   // 510 steps
        LSTM_STEP(0);
        LSTM_STEP(1);
        LSTM_STEP(2);
    }
    LSTM_STEP(0);                        // step 510
    LSTM_STEP(1);                        // step 511

#undef LSTM_STEP

    if (real) {
        __half2 hh = *(__half2*)&hn;
        g_hfin[(size_t)(dir * Bz + bg * 4 + n0) * Hz + e]     = __low2float(hh);
        g_hfin[(size_t)(dir * Bz + bg * 4 + n0 + 1) * Hz + e] = __high2float(hh);
    }
}

// ---------------------------------------------------------------------------
// Kernel 3: final FC + sigmoid
// ---------------------------------------------------------------------------
__global__ void final_fc(const float* __restrict__ fcw,
                         const float* __restrict__ fcb,
                         float* __restrict__ out)
{
    int b = threadIdx.x;
    if (b >= Bz) return;
    float acc = fcb[0];
    const float* hf = g_hfin + b * Hz;
    const float* hb = g_hfin + Bz * Hz + b * Hz;
#pragma unroll
    for (int u = 0; u < Hz; u++) {
        acc = fmaf(hf[u], fcw[u], acc);
        acc = fmaf(hb[u], fcw[Hz + u], acc);
    }
    out[b] = __fdividef(1.0f, 1.0f + __expf(-acc));
}

// ---------------------------------------------------------------------------
extern "C" void kernel_launch(void* const* d_in, const int* in_sizes, int n_in,
                              void* d_out, int out_size)
{
    const int*   x     = (const int*)  d_in[0];
    const float* emb   = (const float*)d_in[1];
    const float* Wih_f = (const float*)d_in[2];
    const float* Whh_f = (const float*)d_in[3];
    const float* bih_f = (const float*)d_in[4];
    const float* bhh_f = (const float*)d_in[5];
    const float* Wih_b = (const float*)d_in[6];
    const float* Whh_b = (const float*)d_in[7];
    const float* bih_b = (const float*)d_in[8];
    const float* bhh_b = (const float*)d_in[9];
    const float* fcw   = (const float*)d_in[10];
    const float* fcb   = (const float*)d_in[11];
    float* out = (float*)d_out;

    cvt_emb<<<VP / 4, 256>>>(emb);
    cvt_wih<<<512, 64>>>(Wih_f, Wih_b);

    dim3 g1(VP / 128, NC / 64);   // 391 x 8
    vocab_gemm<<<g1, 256>>>(bih_f, bhh_f, bih_b, bhh_b);

    dim3 g2(Bz / 4, 2);           // 128 blocks, one wave
    lstm_rec<<<g2, 256>>>(x, Whh_f, Whh_b);

    final_fc<<<1, 256>>>(fcw, fcb, out);
}

// round 14
// speedup vs baseline: 1.1500x; 1.1500x over previous
#include <cuda_runtime.h>
#include <cuda_fp16.h>
#include <cuda_bf16.h>

#define Bz 256
#define Sz 512
#define Ez 100
#define Hz 64
#define Gz 256      // 4*H
#define Vz 50000
#define VP 50048    // padded vocab rows (391*128)
#define NC 512      // 2 dirs * 256 entries
#define KPH 112     // padded K in halfs

// Table layout: [v][dir][cell e][gate i,f,g,o]  (gate-interleaved), fp16
__device__ __half g_tableh[(size_t)VP * NC];      // 51.2 MB (L2-resident)
__device__ __half g_embh[(size_t)VP * KPH];       // padded fp16 embeddings
__device__ __half g_wihh[2 * 256 * KPH];          // permuted fp16 W_ih
__device__ float  g_hfin[2 * Bz * Hz];

// f32-accumulator MMA
#define MMA16816(c0,c1,c2,c3, a0,a1,a2,a3, b0,b1) \
    asm("mma.sync.aligned.m16n8k16.row.col.f32.f16.f16.f32 " \
        "{%0,%1,%2,%3}, {%4,%5,%6,%7}, {%8,%9}, {%0,%1,%2,%3};" \
        : "+f"(c0), "+f"(c1), "+f"(c2), "+f"(c3) \
        : "r"(a0), "r"(a1), "r"(a2), "r"(a3), "r"(b0), "r"(b1))

// packed sigmoid: sigm(x) = 0.5*tanh(0.5x) + 0.5  (f16x2)
#define SIGM2(dst, src, h05) \
    asm("{ .reg .b32 tmp;\n\t" \
        "mul.f16x2 tmp, %1, %2;\n\t" \
        "tanh.approx.f16x2 tmp, tmp;\n\t" \
        "fma.rn.f16x2 %0, tmp, %2, %2; }" \
        : "=r"(dst) : "r"(src), "r"(h05))

#define PRMT(d, a, b, sel) \
    asm("prmt.b32 %0, %1, %2, %3;" : "=r"(d) : "r"(a), "r"(b), "n"(sel))

__device__ __forceinline__ unsigned int tanh2_ap(unsigned int x) {
    unsigned int y;
    asm("tanh.approx.f16x2 %0, %1;" : "=r"(y) : "r"(x));
    return y;
}
__device__ __forceinline__ unsigned int hadd2u(unsigned int a, unsigned int b) {
    unsigned int d;
    asm("add.rn.f16x2 %0, %1, %2;" : "=r"(d) : "r"(a), "r"(b));
    return d;
}
__device__ __forceinline__ unsigned int hmul2u(unsigned int a, unsigned int b) {
    unsigned int d;
    asm("mul.f16x2 %0, %1, %2;" : "=r"(d) : "r"(a), "r"(b));
    return d;
}
__device__ __forceinline__ unsigned int hfma2u(unsigned int a, unsigned int b,
                                               unsigned int c) {
    unsigned int d;
    asm("fma.rn.f16x2 %0, %1, %2, %3;" : "=r"(d) : "r"(a), "r"(b), "r"(c));
    return d;
}
__device__ __forceinline__ unsigned int pkf(float a, float b) {
    __half2 h = __floats2half2_rn(a, b);
    return *(unsigned int*)&h;
}

#define H05C 0x38003800u   // half2(0.5, 0.5)

// packed LSTM cell update: returns h (f16x2), updates cst (f16x2)
__device__ __forceinline__ unsigned int lstm_update(unsigned int ui, unsigned int uf,
                                                    unsigned int ug, unsigned int uo,
                                                    unsigned int& cst) {
    unsigned int si, sf, so;
    SIGM2(si, ui, H05C);
    SIGM2(sf, uf, H05C);
    SIGM2(so, uo, H05C);
    unsigned int tgg = tanh2_ap(ug);
    cst = hfma2u(sf, cst, hmul2u(si, tgg));
    return hmul2u(so, tanh2_ap(cst));
}

// ---------------------------------------------------------------------------
// Kernel 0a: convert embeddings -> fp16 padded [VP][112]
// ---------------------------------------------------------------------------
__global__ __launch_bounds__(256)
void cvt_emb(const float* __restrict__ emb)
{
    int row = blockIdx.x * 4 + (threadIdx.x >> 6);
    int q   = threadIdx.x & 63;            // half2 index within row
    if (q >= KPH / 2) return;
    __half2 v = __half2half2(__float2half(0.0f));
    if (row < Vz && q < 50) {
        float2 f = ((const float2*)emb)[(size_t)row * 50 + q];
        v = __floats2half2_rn(f.x, f.y);
    }
    ((__half2*)g_embh)[(size_t)row * (KPH / 2) + q] = v;
}

// ---------------------------------------------------------------------------
// Kernel 0b: convert W_ih -> fp16, gate-permuted rows: g_wihh[dir][cnew][112]
//            where cnew = 4*e + gate holds W_ih row gate*64 + e.
// ---------------------------------------------------------------------------
__global__ __launch_bounds__(64)
void cvt_wih(const float* __restrict__ Wf, const float* __restrict__ Wb)
{
    int dir  = blockIdx.x >> 8;
    int cnew = blockIdx.x & 255;
    int wrow = (cnew & 3) * 64 + (cnew >> 2);
    const float2* W2 = (const float2*)(dir ? Wb : Wf) + (size_t)wrow * 50;
    int q = threadIdx.x;
    if (q >= KPH / 2) return;
    __half2 v = (q < 50) ? __floats2half2_rn(W2[q].x, W2[q].y)
                         : __half2half2(__float2half(0.0f));
    ((__half2*)g_wihh)[((size_t)dir * 256 + cnew) * (KPH / 2) + q] = v;
}

// ---------------------------------------------------------------------------
// Kernel 1: vocab-table GEMM via HMMA (fp16 operands pre-converted).
// Staging = pure uint4 copies with shift-only indexing. Epilogue unchanged.
// ---------------------------------------------------------------------------
#define LDH 120    // smem row stride in halfs

__global__ __launch_bounds__(256)
void vocab_gemm(const float* __restrict__ bih_f,
                const float* __restrict__ bhh_f,
                const float* __restrict__ bih_b,
                const float* __restrict__ bhh_b)
{
    const int tid  = threadIdx.x;
    const int lane = tid & 31;
    const int w    = tid >> 5;
    const int gid  = lane >> 2;
    const int tg   = lane & 3;
    const int wm   = w & 3;
    const int wn   = w >> 2;

    const int rb = blockIdx.x * 128;
    const int cb = blockIdx.y * 64;
    const int dir = cb >> 8;
    const int gb  = cb & 255;          // column base within dir

    const float* __restrict__ bi = dir ? bih_b : bih_f;
    const float* __restrict__ bh = dir ? bhh_b : bhh_f;

    __shared__ __align__(16) __half As[128 * LDH];
    __shared__ __align__(16) __half Bs[64 * LDH];
    __shared__ float bias_s[64];

    if (tid < 64) {
        int cloc = gb + tid;
        int wrow = (cloc & 3) * 64 + (cloc >> 2);   // gate*64 + e
        bias_s[tid] = bi[wrow] + bh[wrow];
    }

    // Stage A: 128 rows x 14 uint4; 2 threads per row, 7 uint4 each
    {
        int m = tid >> 1, h = tid & 1;
        const uint4* src = (const uint4*)(g_embh + (size_t)(rb + m) * KPH) + h * 7;
        uint4* dst = (uint4*)(As + m * LDH) + h * 7;
#pragma unroll
        for (int i = 0; i < 7; i++) dst[i] = src[i];
    }
    // Stage B: 64 rows x 14 uint4; 4 threads per row
    {
        int m = tid >> 2, q0 = tid & 3;
        const uint4* src = (const uint4*)(g_wihh + ((size_t)dir * 256 + gb + m) * KPH);
        uint4* dst = (uint4*)(Bs + m * LDH);
#pragma unroll
        for (int i = 0; i < 4; i++) {
            int q = q0 + 4 * i;
            if (q < 14) dst[q] = src[q];
        }
    }
    __syncthreads();

    float acc[2][4][4];
#pragma unroll
    for (int mt = 0; mt < 2; mt++)
#pragma unroll
        for (int nt = 0; nt < 4; nt++)
#pragma unroll
            for (int i = 0; i < 4; i++) acc[mt][nt][i] = 0.0f;

#pragma unroll
    for (int kt = 0; kt < 7; kt++) {
        unsigned int a[2][4], b[4][2];
#pragma unroll
        for (int mt = 0; mt < 2; mt++) {
            int r = wm * 32 + mt * 16 + gid;
            const unsigned int* p0 = (const unsigned int*)(As + r * LDH + kt * 16 + 2 * tg);
            const unsigned int* p1 = (const unsigned int*)(As + (r + 8) * LDH + kt * 16 + 2 * tg);
            a[mt][0] = p0[0];
            a[mt][1] = p1[0];
            a[mt][2] = p0[4];
            a[mt][3] = p1[4];
        }
#pragma unroll
        for (int nt = 0; nt < 4; nt++) {
            int n = wn * 32 + nt * 8 + gid;
            const unsigned int* p = (const unsigned int*)(Bs + n * LDH + kt * 16 + 2 * tg);
            b[nt][0] = p[0];
            b[nt][1] = p[4];
        }
#pragma unroll
        for (int mt = 0; mt < 2; mt++)
#pragma unroll
            for (int nt = 0; nt < 4; nt++)
                MMA16816(acc[mt][nt][0], acc[mt][nt][1], acc[mt][nt][2], acc[mt][nt][3],
                         a[mt][0], a[mt][1], a[mt][2], a[mt][3],
                         b[nt][0], b[nt][1]);
    }

#pragma unroll
    for (int mt = 0; mt < 2; mt++) {
#pragma unroll
        for (int nt = 0; nt < 4; nt++) {
            int n = wn * 32 + nt * 8 + 2 * tg;
            float b0 = bias_s[n], b1 = bias_s[n + 1];
            int r0 = rb + wm * 32 + mt * 16 + gid;
            int r1 = r0 + 8;
            *(__half2*)&g_tableh[(size_t)r0 * NC + cb + n] =
                __floats2half2_rn(acc[mt][nt][0] + b0, acc[mt][nt][1] + b1);
            *(__half2*)&g_tableh[(size_t)r1 * NC + cb + n] =
                __floats2half2_rn(acc[mt][nt][2] + b0, acc[mt][nt][3] + b1);
        }
    }
}

// ---------------------------------------------------------------------------
// Kernel 2: LSTM recurrence — R11 structure exactly (chain depth 2,
// pA/qA/pB/qB), plus R12's strictly-cheaper clamped unconditional prefetch.
// CH=4 chains/block, 128 blocks = 1 wave, 1 BAR/step.
// ---------------------------------------------------------------------------
#define HP 72    // h smem row stride (halfs)

__global__ __launch_bounds__(256)
void lstm_rec(const int* __restrict__ x,
              const float* __restrict__ Whh_f,
              const float* __restrict__ Whh_b)
{
    const int tid  = threadIdx.x;
    const int lane = tid & 31;
    const int w    = tid >> 5;
    const int gid  = lane >> 2;
    const int tg   = lane & 3;
    const int e    = w * 8 + gid;       // owned cell
    const int n0   = 2 * tg;            // chains n0, n0+1 (real if tg<2)
    const bool real = (tg < 2);

    const int bg  = blockIdx.x;
    const int dir = blockIdx.y;
    const float* __restrict__ W = dir ? Whh_b : Whh_f;
    const __half* __restrict__ tb = g_tableh + dir * Gz;   // + v*NC + 4e

    __shared__ int toks[4][Sz];
    __shared__ __align__(16) __half h_sh[2][8 * HP];

    for (int p = tid; p < 4 * Sz; p += 256) {
        int r = p >> 9, t_ = p & 511;
        toks[r][t_] = x[(bg * 4 + r) * Sz + t_];
    }
    for (int p = tid; p < 2 * 8 * HP; p += 256)
        ((__half*)h_sh)[p] = __float2half(0.0f);

    // A fragments, permuted-gate packing, fp16:
    //   mt0 rows: gid -> i(e), gid+8 -> f(e);  mt1: g(e), o(e)
    unsigned int afr[2][4][4];
#pragma unroll
    for (int mt = 0; mt < 2; mt++) {
        const float* r0 = W + (size_t)((2 * mt)     * 64 + e) * Hz;
        const float* r1 = W + (size_t)((2 * mt + 1) * 64 + e) * Hz;
#pragma unroll
        for (int kt = 0; kt < 4; kt++) {
            int cb_ = kt * 16 + tg * 2;
            __half2 a0 = __floats2half2_rn(r0[cb_],     r0[cb_ + 1]);
            __half2 a1 = __floats2half2_rn(r1[cb_],     r1[cb_ + 1]);
            __half2 a2 = __floats2half2_rn(r0[cb_ + 8], r0[cb_ + 9]);
            __half2 a3 = __floats2half2_rn(r1[cb_ + 8], r1[cb_ + 9]);
            afr[mt][kt][0] = *(unsigned int*)&a0;
            afr[mt][kt][1] = *(unsigned int*)&a1;
            afr[mt][kt][2] = *(unsigned int*)&a2;
            afr[mt][kt][3] = *(unsigned int*)&a3;
        }
    }

    unsigned int cst = 0u;   // packed f16x2 cell state
    unsigned int hn  = 0u;

    __syncthreads();

    int t = dir ? (Sz - 1) : 0;
    const int dt = dir ? -1 : 1;
    int pb = 0;

    // 3-phase xp ring: xr[ph][chain] = uint2 {(i,f),(g,o)} fp16
    uint2 xr[3][2];
#pragma unroll
    for (int p = 0; p < 3; p++) { xr[p][0] = make_uint2(0u, 0u); xr[p][1] = make_uint2(0u, 0u); }
    if (real) {
        xr[0][0] = *(const uint2*)(tb + (size_t)toks[n0][t] * NC + 4 * e);
        xr[0][1] = *(const uint2*)(tb + (size_t)toks[n0 + 1][t] * NC + 4 * e);
        int t1 = t + dt;
        xr[1][0] = *(const uint2*)(tb + (size_t)toks[n0][t1] * NC + 4 * e);
        xr[1][1] = *(const uint2*)(tb + (size_t)toks[n0 + 1][t1] * NC + 4 * e);
    }

#define LSTM_STEP(PH) do {                                                     \
    unsigned int b0[4], b1[4];                                                 \
    _Pragma("unroll")                                                          \
    for (int kt = 0; kt < 4; kt++) {                                           \
        const unsigned int* hw =                                               \
            (const unsigned int*)(h_sh[pb] + gid * HP + kt * 16 + tg * 2);     \
        b0[kt] = hw[0];                                                        \
        b1[kt] = hw[4];                                                        \
    }                                                                          \
    float pA[4] = {0,0,0,0}, qA[4] = {0,0,0,0};                                \
    float pB[4] = {0,0,0,0}, qB[4] = {0,0,0,0};                                \
    MMA16816(pA[0], pA[1], pA[2], pA[3],                                       \
             afr[0][0][0], afr[0][0][1], afr[0][0][2], afr[0][0][3], b0[0], b1[0]); \
    MMA16816(qA[0], qA[1], qA[2], qA[3],                                       \
             afr[0][2][0], afr[0][2][1], afr[0][2][2], afr[0][2][3], b0[2], b1[2]); \
    MMA16816(pB[0], pB[1], pB[2], pB[3],                                       \
             afr[1][0][0], afr[1][0][1], afr[1][0][2], afr[1][0][3], b0[0], b1[0]); \
    MMA16816(qB[0], qB[1], qB[2], qB[3],                                       \
             afr[1][2][0], afr[1][2][1], afr[1][2][2], afr[1][2][3], b0[2], b1[2]); \
    {   /* prefetch for step s+2 into ring slot (PH+2)%3, clamped t */         \
        const int PH2 = (PH + 2) % 3;                                          \
        if (real) {                                                            \
            int t2 = t + 2 * dt;                                               \
            t2 = t2 < 0 ? 0 : (t2 > Sz - 1 ? Sz - 1 : t2);                     \
            xr[PH2][0] = *(const uint2*)(tb + (size_t)toks[n0][t2] * NC + 4 * e);     \
            xr[PH2][1] = *(const uint2*)(tb + (size_t)toks[n0 + 1][t2] * NC + 4 * e); \
        }                                                                      \
    }                                                                          \
    MMA16816(pA[0], pA[1], pA[2], pA[3],                                       \
             afr[0][1][0], afr[0][1][1], afr[0][1][2], afr[0][1][3], b0[1], b1[1]); \
    MMA16816(qA[0], qA[1], qA[2], qA[3],                                       \
             afr[0][3][0], afr[0][3][1], afr[0][3][2], afr[0][3][3], b0[3], b1[3]); \
    MMA16816(pB[0], pB[1], pB[2], pB[3],                                       \
             afr[1][1][0], afr[1][1][1], afr[1][1][2], afr[1][1][3], b0[1], b1[1]); \
    MMA16816(qB[0], qB[1], qB[2], qB[3],                                       \
             afr[1][3][0], afr[1][3][1], afr[1][3][2], afr[1][3][3], b0[3], b1[3]); \
    unsigned int ui = pkf(pA[0] + qA[0], pA[1] + qA[1]);                       \
    unsigned int uf = pkf(pA[2] + qA[2], pA[3] + qA[3]);                       \
    unsigned int ug = pkf(pB[0] + qB[0], pB[1] + qB[1]);                       \
    unsigned int uo = pkf(pB[2] + qB[2], pB[3] + qB[3]);                       \
    {   /* unpack xp (loaded 2 steps ago) and merge in f16 */                  \
        uint2 c0 = xr[PH][0], c1 = xr[PH][1];                                  \
        unsigned int xi, xf, xg, xo;                                           \
        PRMT(xi, c0.x, c1.x, 0x5410);                                          \
        PRMT(xf, c0.x, c1.x, 0x7632);                                          \
        PRMT(xg, c0.y, c1.y, 0x5410);                                          \
        PRMT(xo, c0.y, c1.y, 0x7632);                                          \
        ui = hadd2u(ui, xi);                                                   \
        uf = hadd2u(uf, xf);                                                   \
        ug = hadd2u(ug, xg);                                                   \
        uo = hadd2u(uo, xo);                                                   \
    }                                                                          \
    hn = lstm_update(ui, uf, ug, uo, cst);                                     \
    if (real) {                                                                \
        __half2 hh = *(__half2*)&hn;                                           \
        h_sh[pb ^ 1][n0 * HP + e]       = __low2half(hh);                      \
        h_sh[pb ^ 1][(n0 + 1) * HP + e] = __high2half(hh);                     \
    }                                                                          \
    __syncthreads();                                                           \
    pb ^= 1;                                                                   \
    t += dt;                                                                   \
} while (0)

    for (int it = 0; it < 170; it++) {   // 510 steps
        LSTM_STEP(0);
        LSTM_STEP(1);
        LSTM_STEP(2);
    }
    LSTM_STEP(0);                        // step 510
    LSTM_STEP(1);                        // step 511

#undef LSTM_STEP

    if (real) {
        __half2 hh = *(__half2*)&hn;
        g_hfin[(size_t)(dir * Bz + bg * 4 + n0) * Hz + e]     = __low2float(hh);
        g_hfin[(size_t)(dir * Bz + bg * 4 + n0 + 1) * Hz + e] = __high2float(hh);
    }
}

// ---------------------------------------------------------------------------
// Kernel 3: final FC + sigmoid
// ---------------------------------------------------------------------------
__global__ void final_fc(const float* __restrict__ fcw,
                         const float* __restrict__ fcb,
                         float* __restrict__ out)
{
    int b = threadIdx.x;
    if (b >= Bz) return;
    float acc = fcb[0];
    const float* hf = g_hfin + b * Hz;
    const float* hb = g_hfin + Bz * Hz + b * Hz;
#pragma unroll
    for (int u = 0; u < Hz; u++) {
        acc = fmaf(hf[u], fcw[u], acc);
        acc = fmaf(hb[u], fcw[Hz + u], acc);
    }
    out[b] = __fdividef(1.0f, 1.0f + __expf(-acc));
}

// ---------------------------------------------------------------------------
extern "C" void kernel_launch(void* const* d_in, const int* in_sizes, int n_in,
                              void* d_out, int out_size)
{
    const int*   x     = (const int*)  d_in[0];
    const float* emb   = (const float*)d_in[1];
    const float* Wih_f = (const float*)d_in[2];
    const float* Whh_f = (const float*)d_in[3];
    const float* bih_f = (const float*)d_in[4];
    const float* bhh_f = (const float*)d_in[5];
    const float* Wih_b = (const float*)d_in[6];
    const float* Whh_b = (const float*)d_in[7];
    const float* bih_b = (const float*)d_in[8];
    const float* bhh_b = (const float*)d_in[9];
    const float* fcw   = (const float*)d_in[10];
    const float* fcb   = (const float*)d_in[11];
    float* out = (float*)d_out;

    cvt_emb<<<VP / 4, 256>>>(emb);
    cvt_wih<<<512, 64>>>(Wih_f, Wih_b);

    dim3 g1(VP / 128, NC / 64);   // 391 x 8
    vocab_gemm<<<g1, 256>>>(bih_f, bhh_f, bih_b, bhh_b);

    dim3 g2(Bz / 4, 2);           // 128 blocks, one wave
    lstm_rec<<<g2, 256>>>(x, Whh_f, Whh_b);

    final_fc<<<1, 256>>>(fcw, fcb, out);
}